// round 1
// baseline (speedup 1.0000x reference)
#include <cuda_runtime.h>

#define Bz 8
#define Lz 512
#define Dz 128

// ---- scratch (device globals: no allocation allowed in kernel_launch) ----
__device__ float g_Q[Bz*Lz*Dz];
__device__ float g_K[Bz*Lz*Dz];
__device__ float g_V[Bz*Lz*Dz];
__device__ float g_P[Bz*Lz*Lz];   // logits, then attn (in-place softmax)
__device__ float g_w[Dz];         // combined score weights
__device__ float g_b[1];          // combined score bias

__device__ __forceinline__ float tanha(float x){
    float y; asm("tanh.approx.f32 %0, %1;" : "=f"(y) : "f"(x)); return y;
}

// ---- combine the three score heads + 1/sqrt(D) into one weight vector ----
__global__ void k_prep(const float* wd, const float* bd, const float* ws,
                       const float* bs, const float* wt, const float* bt){
    int i = threadIdx.x;
    if (i < Dz)
        g_w[i] = 0.08838834764831845f /* 1/sqrt(128) */ + wd[i] + ws[i] + wt[i];
    if (i == 0) g_b[0] = bd[0] + bs[0] + bt[0];
}

// ---- projection: Out[n,o] = sum_i X[n,i]*W[o,i] + bias[o] ----
// CTA tile: 16 n-rows x 64 o-cols. 256 threads: thread = (o_local, 4 n-rows).
__global__ void k_proj(const float* __restrict__ X, const float* __restrict__ W,
                       const float* __restrict__ bias, int which){
    __shared__ __align__(16) float Ws[64*132];   // pad 132: conflict-free f4 reads
    __shared__ __align__(16) float Xs[16*128];
    float* Out = (which == 0) ? g_Q : (which == 1) ? g_K : g_V;

    int n0 = blockIdx.x * 16;
    int o0 = blockIdx.y * 64;
    int tid = threadIdx.x;

    for (int idx = tid; idx < 64*32; idx += 256){
        int o = idx >> 5, i4 = idx & 31;
        *(float4*)&Ws[o*132 + i4*4] = *(const float4*)&W[(o0+o)*Dz + i4*4];
    }
    for (int idx = tid; idx < 16*32; idx += 256){
        int n = idx >> 5, i4 = idx & 31;
        *(float4*)&Xs[n*128 + i4*4] = *(const float4*)&X[(n0+n)*Dz + i4*4];
    }
    __syncthreads();

    int ol = tid & 63;       // output col within tile
    int ng = tid >> 6;       // 0..3 -> rows ng*4 .. ng*4+3
    float acc0=0.f, acc1=0.f, acc2=0.f, acc3=0.f;
    #pragma unroll 8
    for (int i4 = 0; i4 < 32; i4++){
        float4 w = *(float4*)&Ws[ol*132 + i4*4];
        float4 x0 = *(float4*)&Xs[(ng*4+0)*128 + i4*4];
        float4 x1 = *(float4*)&Xs[(ng*4+1)*128 + i4*4];
        float4 x2 = *(float4*)&Xs[(ng*4+2)*128 + i4*4];
        float4 x3 = *(float4*)&Xs[(ng*4+3)*128 + i4*4];
        acc0 += w.x*x0.x + w.y*x0.y + w.z*x0.z + w.w*x0.w;
        acc1 += w.x*x1.x + w.y*x1.y + w.z*x1.z + w.w*x1.w;
        acc2 += w.x*x2.x + w.y*x2.y + w.z*x2.z + w.w*x2.w;
        acc3 += w.x*x3.x + w.y*x3.y + w.z*x3.z + w.w*x3.w;
    }
    float bv = bias[o0 + ol];
    Out[(n0 + ng*4 + 0)*Dz + o0 + ol] = acc0 + bv;
    Out[(n0 + ng*4 + 1)*Dz + o0 + ol] = acc1 + bv;
    Out[(n0 + ng*4 + 2)*Dz + o0 + ol] = acc2 + bv;
    Out[(n0 + ng*4 + 3)*Dz + o0 + ol] = acc3 + bv;
}

// ---- scores: logits[b,q,k] = b_all + sum_d w[d]*tanh(Q[b,q,d]+K[b,k,d]) ----
// CTA = (qtile of 8, b). 256 threads. K staged in smem tiles of 64 rows.
// One thread owns a full 128-d reduction for one (q,k): no cross-thread reduce.
__global__ void k_scores(){
    __shared__ __align__(16) float Ks[64*132];
    __shared__ __align__(16) float Qs[8*132];
    __shared__ __align__(16) float sw[Dz];

    int b  = blockIdx.y;
    int q0 = blockIdx.x * 8;
    int tid = threadIdx.x;

    for (int idx = tid; idx < 8*32; idx += 256){
        int q = idx >> 5, d4 = idx & 31;
        *(float4*)&Qs[q*132 + d4*4] = *(const float4*)&g_Q[(b*Lz + q0 + q)*Dz + d4*4];
    }
    if (tid < Dz) sw[tid] = g_w[tid];
    float ball = g_b[0];

    int kl = tid & 63;       // k within tile; warp lanes have consecutive k
    int qg = tid >> 6;       // 0..3

    for (int kt = 0; kt < 8; kt++){
        __syncthreads();
        for (int idx = tid; idx < 64*32; idx += 256){
            int r = idx >> 5, d4 = idx & 31;
            *(float4*)&Ks[r*132 + d4*4] =
                *(const float4*)&g_K[(b*Lz + kt*64 + r)*Dz + d4*4];
        }
        __syncthreads();
        #pragma unroll
        for (int qs = 0; qs < 2; qs++){
            int q = qs*4 + qg;
            float acc = 0.f;
            #pragma unroll 8
            for (int d4 = 0; d4 < 32; d4++){
                float4 k4 = *(float4*)&Ks[kl*132 + d4*4];
                float4 q4 = *(float4*)&Qs[q*132 + d4*4];
                float4 w4 = *(float4*)&sw[d4*4];
                acc += w4.x * tanha(q4.x + k4.x);
                acc += w4.y * tanha(q4.y + k4.y);
                acc += w4.z * tanha(q4.z + k4.z);
                acc += w4.w * tanha(q4.w + k4.w);
            }
            g_P[(b*Lz + q0 + q)*Lz + kt*64 + kl] = acc + ball;
        }
    }
}

// ---- softmax over last dim (512), in place ----
__global__ void k_softmax(){
    __shared__ float red[16];
    float* p = &g_P[(long)blockIdx.x * Lz];
    int tid = threadIdx.x;                 // 256 threads, 2 elems each
    float a = p[tid], c = p[tid+256];
    float m = fmaxf(a, c);
    for (int s = 16; s; s >>= 1) m = fmaxf(m, __shfl_xor_sync(~0u, m, s));
    if ((tid & 31) == 0) red[tid >> 5] = m;
    __syncthreads();
    if (tid < 8){
        float v = red[tid];
        for (int s = 4; s; s >>= 1) v = fmaxf(v, __shfl_xor_sync(0xff, v, s));
        red[tid] = v;
    }
    __syncthreads();
    m = red[0];
    float e1 = __expf(a - m), e2 = __expf(c - m);
    float s = e1 + e2;
    for (int sh = 16; sh; sh >>= 1) s += __shfl_xor_sync(~0u, s, sh);
    if ((tid & 31) == 0) red[8 + (tid >> 5)] = s;
    __syncthreads();
    if (tid == 0){
        float v = 0.f;
        for (int i = 0; i < 8; i++) v += red[8+i];
        red[8] = v;
    }
    __syncthreads();
    float inv = 1.f / red[8];
    p[tid]     = e1 * inv;
    p[tid+256] = e2 * inv;
}

// ---- out[b,q,:] = sum_k attn[b,q,k] * V[b,k,:] ----
// CTA = (qtile of 8, b). Each warp owns one q; thread owns 4 d's (float4 acc).
__global__ void k_av(float* __restrict__ Out){
    __shared__ __align__(16) float Vs[64*Dz];   // 32 KB; same-k f4 reads: no pad needed
    int b  = blockIdx.y;
    int q0 = blockIdx.x * 8;
    int tid = threadIdx.x;
    int d4 = (tid & 31) * 4;
    int qg = tid >> 5;                          // warp id = q within tile

    float4 acc = make_float4(0.f, 0.f, 0.f, 0.f);
    const float* attn = &g_P[(b*Lz + q0 + qg)*Lz];

    for (int kt = 0; kt < 8; kt++){
        __syncthreads();
        for (int idx = tid; idx < 64*32; idx += 256){
            int r = idx >> 5, c4 = idx & 31;
            *(float4*)&Vs[r*Dz + c4*4] =
                *(const float4*)&g_V[(b*Lz + kt*64 + r)*Dz + c4*4];
        }
        __syncthreads();
        #pragma unroll 4
        for (int k = 0; k < 64; k += 4){
            float4 a4 = *(const float4*)&attn[kt*64 + k];
            float4 v;
            v = *(float4*)&Vs[(k+0)*Dz + d4];
            acc.x += a4.x*v.x; acc.y += a4.x*v.y; acc.z += a4.x*v.z; acc.w += a4.x*v.w;
            v = *(float4*)&Vs[(k+1)*Dz + d4];
            acc.x += a4.y*v.x; acc.y += a4.y*v.y; acc.z += a4.y*v.z; acc.w += a4.y*v.w;
            v = *(float4*)&Vs[(k+2)*Dz + d4];
            acc.x += a4.z*v.x; acc.y += a4.z*v.y; acc.z += a4.z*v.z; acc.w += a4.z*v.w;
            v = *(float4*)&Vs[(k+3)*Dz + d4];
            acc.x += a4.w*v.x; acc.y += a4.w*v.y; acc.z += a4.w*v.z; acc.w += a4.w*v.w;
        }
    }
    *(float4*)&Out[(b*Lz + q0 + qg)*Dz + d4] = acc;
}

extern "C" void kernel_launch(void* const* d_in, const int* in_sizes, int n_in,
                              void* d_out, int out_size){
    const float* query = (const float*)d_in[0];
    const float* key_  = (const float*)d_in[1];
    const float* value = (const float*)d_in[2];
    const float* Wq = (const float*)d_in[3];
    const float* bq = (const float*)d_in[4];
    const float* Wk = (const float*)d_in[5];
    const float* bk = (const float*)d_in[6];
    const float* Wv = (const float*)d_in[7];
    const float* bv = (const float*)d_in[8];
    const float* wd = (const float*)d_in[9];
    const float* bd = (const float*)d_in[10];
    const float* ws = (const float*)d_in[11];
    const float* bs = (const float*)d_in[12];
    const float* wt = (const float*)d_in[13];
    const float* bt = (const float*)d_in[14];
    float* out = (float*)d_out;

    k_prep<<<1, 128>>>(wd, bd, ws, bs, wt, bt);

    dim3 gp(Bz*Lz/16, Dz/64);            // (256, 2)
    k_proj<<<gp, 256>>>(query, Wq, bq, 0);
    k_proj<<<gp, 256>>>(key_,  Wk, bk, 1);
    k_proj<<<gp, 256>>>(value, Wv, bv, 2);

    k_scores <<<dim3(Lz/8, Bz), 256>>>();   // (64, 8)
    k_softmax<<<Bz*Lz, 256>>>();            // 4096 rows
    k_av     <<<dim3(Lz/8, Bz), 256>>>(out);
}

// round 2
// speedup vs baseline: 1.0558x; 1.0558x over previous
#include <cuda_runtime.h>
#include <cuda_fp16.h>

#define Bz 8
#define Lz 512
#define Dz 128
#define D2 64   // Dz/2 half2 pairs

// ---- scratch (device globals; no allocation allowed) ----
__device__ __half2 g_Qh[Bz*Lz*D2];
__device__ __half2 g_Kh[Bz*Lz*D2];
__device__ float   g_V [Bz*Lz*Dz];
__device__ float   g_P [Bz*Lz*Lz];   // attn probabilities
__device__ float2  g_w2[D2];         // combined score weights, d-pairs
__device__ float   g_b[1];

// ---- combine the three score heads + 1/sqrt(D) into one weight vector ----
__global__ void k_prep(const float* wd, const float* bd, const float* ws,
                       const float* bs, const float* wt, const float* bt){
    int i = threadIdx.x;     // 64 threads
    if (i < D2){
        float base = 0.08838834764831845f; // 1/sqrt(128)
        g_w2[i] = make_float2(base + wd[2*i]   + ws[2*i]   + wt[2*i],
                              base + wd[2*i+1] + ws[2*i+1] + wt[2*i+1]);
    }
    if (i == 0) g_b[0] = bd[0] + bs[0] + bt[0];
}

// ---- fused QKV projection: Out[n,o] = sum_i X[n,i]*W[o,i] + b[o] ----
// CTA: 32 n-rows x 64 o-cols, 256 threads, thread = 4 rows x 2 cols.
// Q,K written as packed half2 d-pairs; V written fp32.
__global__ void k_proj(const float* __restrict__ Xq, const float* __restrict__ Xk,
                       const float* __restrict__ Xv,
                       const float* __restrict__ Wq, const float* __restrict__ bq,
                       const float* __restrict__ Wk, const float* __restrict__ bk,
                       const float* __restrict__ Wv, const float* __restrict__ bv){
    __shared__ __align__(16) float Ws[64*128];   // swizzled 16B chunks: exactly 32KB
    __shared__ __align__(16) float Xs[32*128];   // 16KB (reads are warp-broadcast)
    int which = blockIdx.z;
    const float* X    = (which==0) ? Xq : (which==1) ? Xk : Xv;
    const float* W    = (which==0) ? Wq : (which==1) ? Wk : Wv;
    const float* bias = (which==0) ? bq : (which==1) ? bk : bv;

    int n0 = blockIdx.x * 32;
    int o0 = blockIdx.y * 64;
    int tid = threadIdx.x;

    for (int idx = tid; idx < 64*32; idx += 256){
        int o = idx >> 5, c = idx & 31;
        int cs = c ^ (((o >> 1) & 7) << 2);      // conflict-free chunk swizzle
        *(float4*)&Ws[o*128 + cs*4] = *(const float4*)&W[(o0+o)*Dz + c*4];
    }
    for (int idx = tid; idx < 32*32; idx += 256){
        int n = idx >> 5, c = idx & 31;
        *(float4*)&Xs[n*128 + c*4] = *(const float4*)&X[(n0+n)*Dz + c*4];
    }
    __syncthreads();

    int ol = tid & 31;        // col pair: o0 + 2*ol, 2*ol+1
    int ng = tid >> 5;        // row group: rows ng*4 .. ng*4+3 (warp-uniform)
    int r0 = ng * 4;
    int sw = (ol & 7) << 2;

    float a0x=0,a0y=0,a1x=0,a1y=0,a2x=0,a2y=0,a3x=0,a3y=0;
    #pragma unroll 8
    for (int c = 0; c < 32; c++){
        int cs = c ^ sw;
        float4 wa = *(float4*)&Ws[(2*ol  )*128 + cs*4];
        float4 wb = *(float4*)&Ws[(2*ol+1)*128 + cs*4];
        float4 x0 = *(float4*)&Xs[(r0+0)*128 + c*4];
        float4 x1 = *(float4*)&Xs[(r0+1)*128 + c*4];
        float4 x2 = *(float4*)&Xs[(r0+2)*128 + c*4];
        float4 x3 = *(float4*)&Xs[(r0+3)*128 + c*4];
        a0x += wa.x*x0.x + wa.y*x0.y + wa.z*x0.z + wa.w*x0.w;
        a0y += wb.x*x0.x + wb.y*x0.y + wb.z*x0.z + wb.w*x0.w;
        a1x += wa.x*x1.x + wa.y*x1.y + wa.z*x1.z + wa.w*x1.w;
        a1y += wb.x*x1.x + wb.y*x1.y + wb.z*x1.z + wb.w*x1.w;
        a2x += wa.x*x2.x + wa.y*x2.y + wa.z*x2.z + wa.w*x2.w;
        a2y += wb.x*x2.x + wb.y*x2.y + wb.z*x2.z + wb.w*x2.w;
        a3x += wa.x*x3.x + wa.y*x3.y + wa.z*x3.z + wa.w*x3.w;
        a3y += wb.x*x3.x + wb.y*x3.y + wb.z*x3.z + wb.w*x3.w;
    }
    float b0 = bias[o0 + 2*ol], b1 = bias[o0 + 2*ol + 1];
    float rx[4] = {a0x+b0, a1x+b0, a2x+b0, a3x+b0};
    float ry[4] = {a0y+b1, a1y+b1, a2y+b1, a3y+b1};

    if (which == 2){
        #pragma unroll
        for (int r = 0; r < 4; r++)
            *(float2*)&g_V[(n0+r0+r)*Dz + o0 + 2*ol] = make_float2(rx[r], ry[r]);
    } else {
        __half2* dst = which ? g_Kh : g_Qh;
        int d2 = (o0 >> 1) + ol;
        #pragma unroll
        for (int r = 0; r < 4; r++)
            dst[(n0+r0+r)*D2 + d2] = __floats2half2_rn(rx[r], ry[r]);
    }
}

// ---- scores + softmax fused ----
// CTA = (8 q rows, b). 256 threads: warp qg owns q row, lane kl owns 2 k's.
// logits[b,q,k] = b_all + sum_d w[d]*tanh(Q+K)  via tanh.approx.f16x2.
__global__ void k_scores(){
    __shared__ __half2 Ksh[D2][64];   // [d2][k ^ swz]  16KB
    __shared__ __half2 Qsh[8][D2];    // 2KB
    __shared__ float2  sw2[D2];       // 512B
    __shared__ float   sP[8][Lz];     // 16KB logits

    int b  = blockIdx.y;
    int q0 = blockIdx.x * 8;
    int tid = threadIdx.x;
    int kl = tid & 31, qg = tid >> 5;

    for (int idx = tid; idx < 8*D2; idx += 256){
        int q = idx >> 6, d2 = idx & 63;
        Qsh[q][d2] = g_Qh[(b*Lz + q0 + q)*D2 + d2];
    }
    if (tid < D2) sw2[tid] = g_w2[tid];
    float ball = g_b[0];

    for (int kt = 0; kt < 8; kt++){
        __syncthreads();
        for (int idx = tid; idx < 64*D2; idx += 256){
            int r = idx >> 6, d2 = idx & 63;
            Ksh[d2][r ^ d2 & 63] = g_Kh[(b*Lz + kt*64 + r)*D2 + d2];
        }
        __syncthreads();
        float acc0=0.f, acc1=0.f, acc2=0.f, acc3=0.f;
        #pragma unroll 16
        for (int d2 = 0; d2 < D2; d2++){
            __half2 q2 = Qsh[qg][d2];
            int swz = d2 & 63;
            __half2 ka = Ksh[d2][kl ^ swz];
            __half2 kb = Ksh[d2][(kl + 32) ^ swz];
            __half2 sa = __hadd2(q2, ka);
            __half2 sb = __hadd2(q2, kb);
            unsigned ta, tb;
            asm("tanh.approx.f16x2 %0, %1;" : "=r"(ta) : "r"(*(unsigned*)&sa));
            asm("tanh.approx.f16x2 %0, %1;" : "=r"(tb) : "r"(*(unsigned*)&sb));
            float2 fa = __half22float2(*(__half2*)&ta);
            float2 fb = __half22float2(*(__half2*)&tb);
            float2 w = sw2[d2];
            acc0 = fmaf(w.x, fa.x, acc0);
            acc1 = fmaf(w.y, fa.y, acc1);
            acc2 = fmaf(w.x, fb.x, acc2);
            acc3 = fmaf(w.y, fb.y, acc3);
        }
        sP[qg][kt*64 + kl]      = acc0 + acc1 + ball;
        sP[qg][kt*64 + kl + 32] = acc2 + acc3 + ball;
    }
    __syncthreads();

    // warp qg: softmax of row qg (512 elems, 16 per lane), write attn
    float v[16];
    float m = -1e30f;
    #pragma unroll
    for (int j = 0; j < 16; j++){ v[j] = sP[qg][kl + 32*j]; m = fmaxf(m, v[j]); }
    #pragma unroll
    for (int s = 16; s; s >>= 1) m = fmaxf(m, __shfl_xor_sync(~0u, m, s));
    float ssum = 0.f;
    #pragma unroll
    for (int j = 0; j < 16; j++){ v[j] = __expf(v[j] - m); ssum += v[j]; }
    #pragma unroll
    for (int s = 16; s; s >>= 1) ssum += __shfl_xor_sync(~0u, ssum, s);
    float inv = 1.f / ssum;
    float* dst = &g_P[(b*Lz + q0 + qg)*Lz];
    #pragma unroll
    for (int j = 0; j < 16; j++) dst[kl + 32*j] = v[j] * inv;
}

// ---- out[b,q,:] = sum_k attn[b,q,k] * V[b,k,:] ----
// CTA = (16 q, b), 512 threads: warp = q row, lane = 4 d's.
__global__ void k_av(float* __restrict__ Out){
    __shared__ __align__(16) float Vs[64*Dz];   // 32KB
    int b  = blockIdx.y;
    int q0 = blockIdx.x * 16;
    int tid = threadIdx.x;
    int lane = tid & 31, w = tid >> 5;
    int d4 = lane * 4;

    float4 acc = make_float4(0.f, 0.f, 0.f, 0.f);
    const float* attn = &g_P[(b*Lz + q0 + w)*Lz];

    for (int kt = 0; kt < 8; kt++){
        __syncthreads();
        for (int idx = tid; idx < 64*32; idx += 512){
            int r = idx >> 5, c = idx & 31;
            *(float4*)&Vs[r*Dz + c*4] =
                *(const float4*)&g_V[(b*Lz + kt*64 + r)*Dz + c*4];
        }
        __syncthreads();
        #pragma unroll 8
        for (int k = 0; k < 64; k += 4){
            float4 a4 = *(const float4*)&attn[kt*64 + k];
            float4 v;
            v = *(float4*)&Vs[(k+0)*Dz + d4];
            acc.x += a4.x*v.x; acc.y += a4.x*v.y; acc.z += a4.x*v.z; acc.w += a4.x*v.w;
            v = *(float4*)&Vs[(k+1)*Dz + d4];
            acc.x += a4.y*v.x; acc.y += a4.y*v.y; acc.z += a4.y*v.z; acc.w += a4.y*v.w;
            v = *(float4*)&Vs[(k+2)*Dz + d4];
            acc.x += a4.z*v.x; acc.y += a4.z*v.y; acc.z += a4.z*v.z; acc.w += a4.z*v.w;
            v = *(float4*)&Vs[(k+3)*Dz + d4];
            acc.x += a4.w*v.x; acc.y += a4.w*v.y; acc.z += a4.w*v.z; acc.w += a4.w*v.w;
        }
    }
    *(float4*)&Out[(b*Lz + q0 + w)*Dz + d4] = acc;
}

extern "C" void kernel_launch(void* const* d_in, const int* in_sizes, int n_in,
                              void* d_out, int out_size){
    const float* query = (const float*)d_in[0];
    const float* key_  = (const float*)d_in[1];
    const float* value = (const float*)d_in[2];
    const float* Wq = (const float*)d_in[3];
    const float* bq = (const float*)d_in[4];
    const float* Wk = (const float*)d_in[5];
    const float* bk = (const float*)d_in[6];
    const float* Wv = (const float*)d_in[7];
    const float* bv = (const float*)d_in[8];
    const float* wd = (const float*)d_in[9];
    const float* bd = (const float*)d_in[10];
    const float* ws = (const float*)d_in[11];
    const float* bs = (const float*)d_in[12];
    const float* wt = (const float*)d_in[13];
    const float* bt = (const float*)d_in[14];
    float* out = (float*)d_out;

    k_prep<<<1, 64>>>(wd, bd, ws, bs, wt, bt);
    k_proj<<<dim3(Bz*Lz/32, 2, 3), 256>>>(query, key_, value,
                                          Wq, bq, Wk, bk, Wv, bv);
    k_scores<<<dim3(Lz/8, Bz), 256>>>();
    k_av<<<dim3(Lz/16, Bz), 512>>>(out);
}

// round 3
// speedup vs baseline: 1.1881x; 1.1253x over previous
#include <cuda_runtime.h>
#include <cuda_fp16.h>

#define Bz 8
#define Lz 512
#define Dz 128
#define D2 64   // Dz/2 half2 pairs

// ---- scratch (device globals; no allocation allowed) ----
__device__ __half2 g_Qh[Bz*Lz*D2];
__device__ __half2 g_Kh[Bz*Lz*D2];
__device__ float   g_V [Bz*Lz*Dz];
__device__ float   g_P [Bz*Lz*Lz];   // attn probabilities
__device__ float2  g_w2[D2];         // combined score weights, d-pairs
__device__ float   g_b[1];

// ---- combine the three score heads + 1/sqrt(D) into one weight vector ----
__global__ void k_prep(const float* wd, const float* bd, const float* ws,
                       const float* bs, const float* wt, const float* bt){
    int i = threadIdx.x;     // 64 threads
    if (i < D2){
        float base = 0.08838834764831845f; // 1/sqrt(128)
        g_w2[i] = make_float2(base + wd[2*i]   + ws[2*i]   + wt[2*i],
                              base + wd[2*i+1] + ws[2*i+1] + wt[2*i+1]);
    }
    if (i == 0) g_b[0] = bd[0] + bs[0] + bt[0];
}

// ---- fused QKV projection: Out[n,o] = sum_i X[n,i]*W[o,i] + b[o] ----
// CTA: 32 n-rows x 64 o-cols, 256 threads, thread = 4 rows x 2 cols.
// Q,K written as packed half2 d-pairs; V written fp32.
__global__ void k_proj(const float* __restrict__ Xq, const float* __restrict__ Xk,
                       const float* __restrict__ Xv,
                       const float* __restrict__ Wq, const float* __restrict__ bq,
                       const float* __restrict__ Wk, const float* __restrict__ bk,
                       const float* __restrict__ Wv, const float* __restrict__ bv){
    __shared__ __align__(16) float Ws[64*128];   // swizzled 16B chunks: exactly 32KB
    __shared__ __align__(16) float Xs[32*128];   // 16KB (reads are warp-broadcast)
    int which = blockIdx.z;
    const float* X    = (which==0) ? Xq : (which==1) ? Xk : Xv;
    const float* W    = (which==0) ? Wq : (which==1) ? Wk : Wv;
    const float* bias = (which==0) ? bq : (which==1) ? bk : bv;

    int n0 = blockIdx.x * 32;
    int o0 = blockIdx.y * 64;
    int tid = threadIdx.x;

    for (int idx = tid; idx < 64*32; idx += 256){
        int o = idx >> 5, c = idx & 31;
        int cs = c ^ (((o >> 1) & 7) << 2);      // conflict-free chunk swizzle
        *(float4*)&Ws[o*128 + cs*4] = *(const float4*)&W[(o0+o)*Dz + c*4];
    }
    for (int idx = tid; idx < 32*32; idx += 256){
        int n = idx >> 5, c = idx & 31;
        *(float4*)&Xs[n*128 + c*4] = *(const float4*)&X[(n0+n)*Dz + c*4];
    }
    __syncthreads();

    int ol = tid & 31;        // col pair: o0 + 2*ol, 2*ol+1
    int ng = tid >> 5;        // row group: rows ng*4 .. ng*4+3 (warp-uniform)
    int r0 = ng * 4;
    int sw = (ol & 7) << 2;

    float a0x=0,a0y=0,a1x=0,a1y=0,a2x=0,a2y=0,a3x=0,a3y=0;
    #pragma unroll 8
    for (int c = 0; c < 32; c++){
        int cs = c ^ sw;
        float4 wa = *(float4*)&Ws[(2*ol  )*128 + cs*4];
        float4 wb = *(float4*)&Ws[(2*ol+1)*128 + cs*4];
        float4 x0 = *(float4*)&Xs[(r0+0)*128 + c*4];
        float4 x1 = *(float4*)&Xs[(r0+1)*128 + c*4];
        float4 x2 = *(float4*)&Xs[(r0+2)*128 + c*4];
        float4 x3 = *(float4*)&Xs[(r0+3)*128 + c*4];
        a0x += wa.x*x0.x + wa.y*x0.y + wa.z*x0.z + wa.w*x0.w;
        a0y += wb.x*x0.x + wb.y*x0.y + wb.z*x0.z + wb.w*x0.w;
        a1x += wa.x*x1.x + wa.y*x1.y + wa.z*x1.z + wa.w*x1.w;
        a1y += wb.x*x1.x + wb.y*x1.y + wb.z*x1.z + wb.w*x1.w;
        a2x += wa.x*x2.x + wa.y*x2.y + wa.z*x2.z + wa.w*x2.w;
        a2y += wb.x*x2.x + wb.y*x2.y + wb.z*x2.z + wb.w*x2.w;
        a3x += wa.x*x3.x + wa.y*x3.y + wa.z*x3.z + wa.w*x3.w;
        a3y += wb.x*x3.x + wb.y*x3.y + wb.z*x3.z + wb.w*x3.w;
    }
    float b0 = bias[o0 + 2*ol], b1 = bias[o0 + 2*ol + 1];
    float rx[4] = {a0x+b0, a1x+b0, a2x+b0, a3x+b0};
    float ry[4] = {a0y+b1, a1y+b1, a2y+b1, a3y+b1};

    if (which == 2){
        #pragma unroll
        for (int r = 0; r < 4; r++)
            *(float2*)&g_V[(n0+r0+r)*Dz + o0 + 2*ol] = make_float2(rx[r], ry[r]);
    } else {
        __half2* dst = which ? g_Kh : g_Qh;
        int d2 = (o0 >> 1) + ol;
        #pragma unroll
        for (int r = 0; r < 4; r++)
            dst[(n0+r0+r)*D2 + d2] = __floats2half2_rn(rx[r], ry[r]);
    }
}

// ---- scores + softmax fused ----
// CTA = (8 q rows, b). 256 threads: warp qg owns q row, lane kl owns 2 k's.
// logits[b,q,k] = b_all + sum_d w[d]*tanh(Q+K)  via tanh.approx.f16x2.
__global__ void k_scores(){
    __shared__ __half2 Ksh[D2][64];   // [d2][k ^ swz]  16KB
    __shared__ __half2 Qsh[8][D2];    // 2KB
    __shared__ float2  sw2[D2];       // 512B
    __shared__ float   sP[8][Lz];     // 16KB logits

    int b  = blockIdx.y;
    int q0 = blockIdx.x * 8;
    int tid = threadIdx.x;
    int kl = tid & 31, qg = tid >> 5;

    for (int idx = tid; idx < 8*D2; idx += 256){
        int q = idx >> 6, d2 = idx & 63;
        Qsh[q][d2] = g_Qh[(b*Lz + q0 + q)*D2 + d2];
    }
    if (tid < D2) sw2[tid] = g_w2[tid];
    float ball = g_b[0];

    for (int kt = 0; kt < 8; kt++){
        __syncthreads();
        for (int idx = tid; idx < 64*D2; idx += 256){
            int r = idx >> 6, d2 = idx & 63;
            Ksh[d2][r ^ (d2 & 63)] = g_Kh[(b*Lz + kt*64 + r)*D2 + d2];
        }
        __syncthreads();
        float acc0=0.f, acc1=0.f, acc2=0.f, acc3=0.f;
        #pragma unroll 16
        for (int d2 = 0; d2 < D2; d2++){
            __half2 q2 = Qsh[qg][d2];
            int swz = d2 & 63;
            __half2 ka = Ksh[d2][kl ^ swz];
            __half2 kb = Ksh[d2][(kl + 32) ^ swz];
            __half2 sa = __hadd2(q2, ka);
            __half2 sb = __hadd2(q2, kb);
            unsigned ta, tb;
            asm("tanh.approx.f16x2 %0, %1;" : "=r"(ta) : "r"(*(unsigned*)&sa));
            asm("tanh.approx.f16x2 %0, %1;" : "=r"(tb) : "r"(*(unsigned*)&sb));
            float2 fa = __half22float2(*(__half2*)&ta);
            float2 fb = __half22float2(*(__half2*)&tb);
            float2 w = sw2[d2];
            acc0 = fmaf(w.x, fa.x, acc0);
            acc1 = fmaf(w.y, fa.y, acc1);
            acc2 = fmaf(w.x, fb.x, acc2);
            acc3 = fmaf(w.y, fb.y, acc3);
        }
        sP[qg][kt*64 + kl]      = acc0 + acc1 + ball;
        sP[qg][kt*64 + kl + 32] = acc2 + acc3 + ball;
    }
    __syncthreads();

    // warp qg: softmax of row qg (512 elems, 16 per lane), write attn
    float v[16];
    float m = -1e30f;
    #pragma unroll
    for (int j = 0; j < 16; j++){ v[j] = sP[qg][kl + 32*j]; m = fmaxf(m, v[j]); }
    #pragma unroll
    for (int s = 16; s; s >>= 1) m = fmaxf(m, __shfl_xor_sync(~0u, m, s));
    float ssum = 0.f;
    #pragma unroll
    for (int j = 0; j < 16; j++){ v[j] = __expf(v[j] - m); ssum += v[j]; }
    #pragma unroll
    for (int s = 16; s; s >>= 1) ssum += __shfl_xor_sync(~0u, ssum, s);
    float inv = 1.f / ssum;
    float* dst = &g_P[(b*Lz + q0 + qg)*Lz];
    #pragma unroll
    for (int j = 0; j < 16; j++) dst[kl + 32*j] = v[j] * inv;
}

// ---- out[b,q,:] = sum_k attn[b,q,k] * V[b,k,:] ----
// CTA = (32 q, b), 256 threads, 8 warps. Warp owns 4 q rows; lane owns 4 d.
// Register tiling: 1 LDS.128 of V feeds 16 lane-FMAs (crossbar-balanced).
// Attn comes from coalesced LDG into regs, broadcast per-k via shfl.
__global__ void k_av(float* __restrict__ Out){
    __shared__ __align__(16) float4 Vs[64][32];   // [k][d4] 32KB
    int b  = blockIdx.y;
    int q0 = blockIdx.x * 32;
    int tid = threadIdx.x;
    int lane = tid & 31, w = tid >> 5;
    int qb = q0 + w*4;                            // warp's first q row

    const float* P = &g_P[(b*Lz + qb)*Lz];        // 4 rows, stride Lz

    float4 acc0 = make_float4(0.f,0.f,0.f,0.f);
    float4 acc1 = acc0, acc2 = acc0, acc3 = acc0;

    for (int kt = 0; kt < 8; kt++){
        __syncthreads();
        for (int idx = tid; idx < 64*32; idx += 256){
            int r = idx >> 5, c = idx & 31;
            Vs[r][c] = *(const float4*)&g_V[(b*Lz + kt*64 + r)*Dz + c*4];
        }
        // prefetch this tile's attn (2 chunks x 4 q) while Vs loads land
        float a00 = P[0*Lz + kt*64 + lane],      a01 = P[1*Lz + kt*64 + lane];
        float a02 = P[2*Lz + kt*64 + lane],      a03 = P[3*Lz + kt*64 + lane];
        float a10 = P[0*Lz + kt*64 + 32 + lane], a11 = P[1*Lz + kt*64 + 32 + lane];
        float a12 = P[2*Lz + kt*64 + 32 + lane], a13 = P[3*Lz + kt*64 + 32 + lane];
        __syncthreads();

        #pragma unroll 4
        for (int j = 0; j < 32; j++){
            float4 v = Vs[j][lane];
            float p0 = __shfl_sync(~0u, a00, j);
            float p1 = __shfl_sync(~0u, a01, j);
            float p2 = __shfl_sync(~0u, a02, j);
            float p3 = __shfl_sync(~0u, a03, j);
            acc0.x += p0*v.x; acc0.y += p0*v.y; acc0.z += p0*v.z; acc0.w += p0*v.w;
            acc1.x += p1*v.x; acc1.y += p1*v.y; acc1.z += p1*v.z; acc1.w += p1*v.w;
            acc2.x += p2*v.x; acc2.y += p2*v.y; acc2.z += p2*v.z; acc2.w += p2*v.w;
            acc3.x += p3*v.x; acc3.y += p3*v.y; acc3.z += p3*v.z; acc3.w += p3*v.w;
        }
        #pragma unroll 4
        for (int j = 0; j < 32; j++){
            float4 v = Vs[32 + j][lane];
            float p0 = __shfl_sync(~0u, a10, j);
            float p1 = __shfl_sync(~0u, a11, j);
            float p2 = __shfl_sync(~0u, a12, j);
            float p3 = __shfl_sync(~0u, a13, j);
            acc0.x += p0*v.x; acc0.y += p0*v.y; acc0.z += p0*v.z; acc0.w += p0*v.w;
            acc1.x += p1*v.x; acc1.y += p1*v.y; acc1.z += p1*v.z; acc1.w += p1*v.w;
            acc2.x += p2*v.x; acc2.y += p2*v.y; acc2.z += p2*v.z; acc2.w += p2*v.w;
            acc3.x += p3*v.x; acc3.y += p3*v.y; acc3.z += p3*v.z; acc3.w += p3*v.w;
        }
    }
    *(float4*)&Out[(b*Lz + qb + 0)*Dz + lane*4] = acc0;
    *(float4*)&Out[(b*Lz + qb + 1)*Dz + lane*4] = acc1;
    *(float4*)&Out[(b*Lz + qb + 2)*Dz + lane*4] = acc2;
    *(float4*)&Out[(b*Lz + qb + 3)*Dz + lane*4] = acc3;
}

extern "C" void kernel_launch(void* const* d_in, const int* in_sizes, int n_in,
                              void* d_out, int out_size){
    const float* query = (const float*)d_in[0];
    const float* key_  = (const float*)d_in[1];
    const float* value = (const float*)d_in[2];
    const float* Wq = (const float*)d_in[3];
    const float* bq = (const float*)d_in[4];
    const float* Wk = (const float*)d_in[5];
    const float* bk = (const float*)d_in[6];
    const float* Wv = (const float*)d_in[7];
    const float* bv = (const float*)d_in[8];
    const float* wd = (const float*)d_in[9];
    const float* bd = (const float*)d_in[10];
    const float* ws = (const float*)d_in[11];
    const float* bs = (const float*)d_in[12];
    const float* wt = (const float*)d_in[13];
    const float* bt = (const float*)d_in[14];
    float* out = (float*)d_out;

    k_prep<<<1, 64>>>(wd, bd, ws, bs, wt, bt);
    k_proj<<<dim3(Bz*Lz/32, 2, 3), 256>>>(query, key_, value,
                                          Wq, bq, Wk, bk, Wv, bv);
    k_scores<<<dim3(Lz/8, Bz), 256>>>();
    k_av<<<dim3(Lz/32, Bz), 256>>>(out);
}

// round 5
// speedup vs baseline: 1.2850x; 1.0816x over previous
#include <cuda_runtime.h>
#include <cuda_fp16.h>

#define Bz 8
#define Lz 512
#define Dz 128
#define D2 64   // Dz/2 half2 pairs

// ---- scratch (device globals; no allocation allowed) ----
__device__ __half2 g_Qh[Bz*Lz*D2];
__device__ __half2 g_Kh[Bz*Lz*D2];
__device__ float   g_V [Bz*Lz*Dz];
__device__ float   g_P [Bz*Lz*Lz];   // attn probabilities
__device__ float2  g_w2[D2];         // combined score weights, d-pairs
__device__ float   g_b[1];

__device__ __forceinline__ void cp16(unsigned smem, const void* g){
    asm volatile("cp.async.ca.shared.global [%0], [%1], 16;" :: "r"(smem), "l"(g));
}

// ---- combine the three score heads + 1/sqrt(D) into one weight vector ----
__global__ void k_prep(const float* wd, const float* bd, const float* ws,
                       const float* bs, const float* wt, const float* bt){
    int i = threadIdx.x;     // 64 threads
    if (i < D2){
        float base = 0.08838834764831845f; // 1/sqrt(128)
        g_w2[i] = make_float2(base + wd[2*i]   + ws[2*i]   + wt[2*i],
                              base + wd[2*i+1] + ws[2*i+1] + wt[2*i+1]);
    }
    if (i == 0) g_b[0] = bd[0] + bs[0] + bt[0];
}

// ---- fused QKV projection: Out[n,o] = sum_i X[n,i]*W[o,i] + b[o] ----
__global__ void k_proj(const float* __restrict__ Xq, const float* __restrict__ Xk,
                       const float* __restrict__ Xv,
                       const float* __restrict__ Wq, const float* __restrict__ bq,
                       const float* __restrict__ Wk, const float* __restrict__ bk,
                       const float* __restrict__ Wv, const float* __restrict__ bv){
    __shared__ __align__(16) float Ws[64*128];   // swizzled 16B chunks: 32KB
    __shared__ __align__(16) float Xs[32*128];   // 16KB
    int which = blockIdx.z;
    const float* X    = (which==0) ? Xq : (which==1) ? Xk : Xv;
    const float* W    = (which==0) ? Wq : (which==1) ? Wk : Wv;
    const float* bias = (which==0) ? bq : (which==1) ? bk : bv;

    int n0 = blockIdx.x * 32;
    int o0 = blockIdx.y * 64;
    int tid = threadIdx.x;

    for (int idx = tid; idx < 64*32; idx += 256){
        int o = idx >> 5, c = idx & 31;
        int cs = c ^ (((o >> 1) & 7) << 2);
        *(float4*)&Ws[o*128 + cs*4] = *(const float4*)&W[(o0+o)*Dz + c*4];
    }
    for (int idx = tid; idx < 32*32; idx += 256){
        int n = idx >> 5, c = idx & 31;
        *(float4*)&Xs[n*128 + c*4] = *(const float4*)&X[(n0+n)*Dz + c*4];
    }
    __syncthreads();

    int ol = tid & 31;
    int ng = tid >> 5;
    int r0 = ng * 4;
    int sw = (ol & 7) << 2;

    float a0x=0,a0y=0,a1x=0,a1y=0,a2x=0,a2y=0,a3x=0,a3y=0;
    #pragma unroll 8
    for (int c = 0; c < 32; c++){
        int cs = c ^ sw;
        float4 wa = *(float4*)&Ws[(2*ol  )*128 + cs*4];
        float4 wb = *(float4*)&Ws[(2*ol+1)*128 + cs*4];
        float4 x0 = *(float4*)&Xs[(r0+0)*128 + c*4];
        float4 x1 = *(float4*)&Xs[(r0+1)*128 + c*4];
        float4 x2 = *(float4*)&Xs[(r0+2)*128 + c*4];
        float4 x3 = *(float4*)&Xs[(r0+3)*128 + c*4];
        a0x += wa.x*x0.x + wa.y*x0.y + wa.z*x0.z + wa.w*x0.w;
        a0y += wb.x*x0.x + wb.y*x0.y + wb.z*x0.z + wb.w*x0.w;
        a1x += wa.x*x1.x + wa.y*x1.y + wa.z*x1.z + wa.w*x1.w;
        a1y += wb.x*x1.x + wb.y*x1.y + wb.z*x1.z + wb.w*x1.w;
        a2x += wa.x*x2.x + wa.y*x2.y + wa.z*x2.z + wa.w*x2.w;
        a2y += wb.x*x2.x + wb.y*x2.y + wb.z*x2.z + wb.w*x2.w;
        a3x += wa.x*x3.x + wa.y*x3.y + wa.z*x3.z + wa.w*x3.w;
        a3y += wb.x*x3.x + wb.y*x3.y + wb.z*x3.z + wb.w*x3.w;
    }
    float b0 = bias[o0 + 2*ol], b1 = bias[o0 + 2*ol + 1];
    float rx[4] = {a0x+b0, a1x+b0, a2x+b0, a3x+b0};
    float ry[4] = {a0y+b1, a1y+b1, a2y+b1, a3y+b1};

    if (which == 2){
        #pragma unroll
        for (int r = 0; r < 4; r++)
            *(float2*)&g_V[(n0+r0+r)*Dz + o0 + 2*ol] = make_float2(rx[r], ry[r]);
    } else {
        __half2* dst = which ? g_Kh : g_Qh;
        int d2 = (o0 >> 1) + ol;
        #pragma unroll
        for (int r = 0; r < 4; r++)
            dst[(n0+r0+r)*D2 + d2] = __floats2half2_rn(rx[r], ry[r]);
    }
}

// ---- scores + softmax fused (unchanged) ----
__global__ void k_scores(){
    __shared__ __half2 Ksh[D2][64];
    __shared__ __half2 Qsh[8][D2];
    __shared__ float2  sw2[D2];
    __shared__ float   sP[8][Lz];

    int b  = blockIdx.y;
    int q0 = blockIdx.x * 8;
    int tid = threadIdx.x;
    int kl = tid & 31, qg = tid >> 5;

    for (int idx = tid; idx < 8*D2; idx += 256){
        int q = idx >> 6, d2 = idx & 63;
        Qsh[q][d2] = g_Qh[(b*Lz + q0 + q)*D2 + d2];
    }
    if (tid < D2) sw2[tid] = g_w2[tid];
    float ball = g_b[0];

    for (int kt = 0; kt < 8; kt++){
        __syncthreads();
        for (int idx = tid; idx < 64*D2; idx += 256){
            int r = idx >> 6, d2 = idx & 63;
            Ksh[d2][r ^ (d2 & 63)] = g_Kh[(b*Lz + kt*64 + r)*D2 + d2];
        }
        __syncthreads();
        float acc0=0.f, acc1=0.f, acc2=0.f, acc3=0.f;
        #pragma unroll 16
        for (int d2 = 0; d2 < D2; d2++){
            __half2 q2 = Qsh[qg][d2];
            int swz = d2 & 63;
            __half2 ka = Ksh[d2][kl ^ swz];
            __half2 kb = Ksh[d2][(kl + 32) ^ swz];
            __half2 sa = __hadd2(q2, ka);
            __half2 sb = __hadd2(q2, kb);
            unsigned ta, tb;
            asm("tanh.approx.f16x2 %0, %1;" : "=r"(ta) : "r"(*(unsigned*)&sa));
            asm("tanh.approx.f16x2 %0, %1;" : "=r"(tb) : "r"(*(unsigned*)&sb));
            float2 fa = __half22float2(*(__half2*)&ta);
            float2 fb = __half22float2(*(__half2*)&tb);
            float2 w = sw2[d2];
            acc0 = fmaf(w.x, fa.x, acc0);
            acc1 = fmaf(w.y, fa.y, acc1);
            acc2 = fmaf(w.x, fb.x, acc2);
            acc3 = fmaf(w.y, fb.y, acc3);
        }
        sP[qg][kt*64 + kl]      = acc0 + acc1 + ball;
        sP[qg][kt*64 + kl + 32] = acc2 + acc3 + ball;
    }
    __syncthreads();

    float v[16];
    float m = -1e30f;
    #pragma unroll
    for (int j = 0; j < 16; j++){ v[j] = sP[qg][kl + 32*j]; m = fmaxf(m, v[j]); }
    #pragma unroll
    for (int s = 16; s; s >>= 1) m = fmaxf(m, __shfl_xor_sync(~0u, m, s));
    float ssum = 0.f;
    #pragma unroll
    for (int j = 0; j < 16; j++){ v[j] = __expf(v[j] - m); ssum += v[j]; }
    #pragma unroll
    for (int s = 16; s; s >>= 1) ssum += __shfl_xor_sync(~0u, ssum, s);
    float inv = 1.f / ssum;
    float* dst = &g_P[(b*Lz + q0 + qg)*Lz];
    #pragma unroll
    for (int j = 0; j < 16; j++) dst[kl + 32*j] = v[j] * inv;
}

// ---- out[b,q,:] = sum_k attn[b,q,k] * V[b,k,:] ----
// CTA = 32 q, 256 thr, 8 warps; warp owns 4 q, lane owns 4 d.
// k tiled by 32, double-buffered via cp.async (V + attn tiles).
// attn read via broadcast LDS (uniform addr) — no SHFL chains.
__global__ void k_av(float* __restrict__ Out){
    __shared__ __align__(16) float Vs[2][32][Dz];   // 2 x 16KB
    __shared__ __align__(16) float aP[2][32][32];   // 2 x 4KB
    int b  = blockIdx.y;
    int q0 = blockIdx.x * 32;
    int tid = threadIdx.x;
    int lane = tid & 31, w = tid >> 5;
    int qb = w * 4;                                  // warp's q group (local)

    const float* Vg = &g_V[(b*Lz)*Dz];
    const float* Pg = &g_P[(b*Lz + q0)*Lz];

    // V fill: 32x128 floats = 1024 f4; 4 f4/thread, linear mapping.
    // row = (tid>>5) + i*8, col4 = tid&31, smem byte off = (tid + i*256)*16.
    int vrow0 = tid >> 5, vcol = (tid & 31) * 4;
    // aP fill: 32x32 floats = 256 f4; 1 f4/thread. row = tid>>3, col = (tid&7)*4.
    int prow = tid >> 3, pcol = (tid & 7) * 4;

    unsigned sV0 = (unsigned)__cvta_generic_to_shared(&Vs[0][0][0]) + tid*16u;
    unsigned sV1 = (unsigned)__cvta_generic_to_shared(&Vs[1][0][0]) + tid*16u;
    unsigned sA0 = (unsigned)__cvta_generic_to_shared(&aP[0][prow][pcol]);
    unsigned sA1 = (unsigned)__cvta_generic_to_shared(&aP[1][prow][pcol]);

    // prefetch stage 0 (k0 = 0)
    {
        #pragma unroll
        for (int i = 0; i < 4; i++)
            cp16(sV0 + i*4096u, &Vg[(vrow0 + i*8)*Dz + vcol]);
        cp16(sA0, &Pg[prow*Lz + pcol]);
        asm volatile("cp.async.commit_group;");
    }

    float4 acc0 = make_float4(0.f,0.f,0.f,0.f);
    float4 acc1 = acc0, acc2 = acc0, acc3 = acc0;

    for (int kt = 0; kt < 16; kt++){
        int buf = kt & 1;
        if (kt + 1 < 16){
            int k0 = (kt + 1) * 32;
            unsigned sV = buf ? sV0 : sV1;
            unsigned sA = buf ? sA0 : sA1;
            #pragma unroll
            for (int i = 0; i < 4; i++)
                cp16(sV + i*4096u, &Vg[(k0 + vrow0 + i*8)*Dz + vcol]);
            cp16(sA, &Pg[prow*Lz + k0 + pcol]);
            asm volatile("cp.async.commit_group;");
            asm volatile("cp.async.wait_group 1;");
        } else {
            asm volatile("cp.async.wait_group 0;");
        }
        __syncthreads();

        #pragma unroll 8
        for (int j = 0; j < 32; j++){
            float4 v = *(const float4*)&Vs[buf][j][lane*4];
            float p0 = aP[buf][qb+0][j];     // uniform addr -> broadcast LDS
            float p1 = aP[buf][qb+1][j];
            float p2 = aP[buf][qb+2][j];
            float p3 = aP[buf][qb+3][j];
            acc0.x += p0*v.x; acc0.y += p0*v.y; acc0.z += p0*v.z; acc0.w += p0*v.w;
            acc1.x += p1*v.x; acc1.y += p1*v.y; acc1.z += p1*v.z; acc1.w += p1*v.w;
            acc2.x += p2*v.x; acc2.y += p2*v.y; acc2.z += p2*v.z; acc2.w += p2*v.w;
            acc3.x += p3*v.x; acc3.y += p3*v.y; acc3.z += p3*v.z; acc3.w += p3*v.w;
        }
        __syncthreads();
    }
    *(float4*)&Out[(b*Lz + q0 + qb + 0)*Dz + lane*4] = acc0;
    *(float4*)&Out[(b*Lz + q0 + qb + 1)*Dz + lane*4] = acc1;
    *(float4*)&Out[(b*Lz + q0 + qb + 2)*Dz + lane*4] = acc2;
    *(float4*)&Out[(b*Lz + q0 + qb + 3)*Dz + lane*4] = acc3;
}

extern "C" void kernel_launch(void* const* d_in, const int* in_sizes, int n_in,
                              void* d_out, int out_size){
    const float* query = (const float*)d_in[0];
    const float* key_  = (const float*)d_in[1];
    const float* value = (const float*)d_in[2];
    const float* Wq = (const float*)d_in[3];
    const float* bq = (const float*)d_in[4];
    const float* Wk = (const float*)d_in[5];
    const float* bk = (const float*)d_in[6];
    const float* Wv = (const float*)d_in[7];
    const float* bv = (const float*)d_in[8];
    const float* wd = (const float*)d_in[9];
    const float* bd = (const float*)d_in[10];
    const float* ws = (const float*)d_in[11];
    const float* bs = (const float*)d_in[12];
    const float* wt = (const float*)d_in[13];
    const float* bt = (const float*)d_in[14];
    float* out = (float*)d_out;

    k_prep<<<1, 64>>>(wd, bd, ws, bs, wt, bt);
    k_proj<<<dim3(Bz*Lz/32, 2, 3), 256>>>(query, key_, value,
                                          Wq, bq, Wk, bk, Wv, bv);
    k_scores<<<dim3(Lz/8, Bz), 256>>>();
    k_av<<<dim3(Lz/32, Bz), 256>>>(out);
}

// round 7
// speedup vs baseline: 1.3440x; 1.0459x over previous
#include <cuda_runtime.h>
#include <cuda_fp16.h>

#define Bz 8
#define Lz 512
#define Dz 128
#define D2 64   // Dz/2 half2 pairs

// ---- scratch (device globals; no allocation allowed) ----
__device__ __half2 g_Qh[Bz*Lz*D2];
__device__ __half2 g_Kh[Bz*Lz*D2];
__device__ float   g_V [Bz*Lz*Dz];
__device__ float   g_P [Bz*Lz*Lz];   // attn probabilities
__device__ __half2 g_w2h[D2];        // combined score weights (half2)
__device__ float   g_b[1];

__device__ __forceinline__ void cp16(unsigned smem, const void* g){
    asm volatile("cp.async.ca.shared.global [%0], [%1], 16;" :: "r"(smem), "l"(g));
}

// ---- combine the three score heads + 1/sqrt(D) into one weight vector ----
__global__ void k_prep(const float* wd, const float* bd, const float* ws,
                       const float* bs, const float* wt, const float* bt){
    int i = threadIdx.x;     // 64 threads
    if (i < D2){
        float base = 0.08838834764831845f; // 1/sqrt(128)
        float wx = base + wd[2*i]   + ws[2*i]   + wt[2*i];
        float wy = base + wd[2*i+1] + ws[2*i+1] + wt[2*i+1];
        g_w2h[i] = __floats2half2_rn(wx, wy);
    }
    if (i == 0) g_b[0] = bd[0] + bs[0] + bt[0];
}

// ---- fused QKV projection: Out[n,o] = sum_i X[n,i]*W[o,i] + b[o] ----
__global__ void k_proj(const float* __restrict__ Xq, const float* __restrict__ Xk,
                       const float* __restrict__ Xv,
                       const float* __restrict__ Wq, const float* __restrict__ bq,
                       const float* __restrict__ Wk, const float* __restrict__ bk,
                       const float* __restrict__ Wv, const float* __restrict__ bv){
    __shared__ __align__(16) float Ws[64*128];   // swizzled 16B chunks: 32KB
    __shared__ __align__(16) float Xs[32*128];   // 16KB
    int which = blockIdx.z;
    const float* X    = (which==0) ? Xq : (which==1) ? Xk : Xv;
    const float* W    = (which==0) ? Wq : (which==1) ? Wk : Wv;
    const float* bias = (which==0) ? bq : (which==1) ? bk : bv;

    int n0 = blockIdx.x * 32;
    int o0 = blockIdx.y * 64;
    int tid = threadIdx.x;

    for (int idx = tid; idx < 64*32; idx += 256){
        int o = idx >> 5, c = idx & 31;
        int cs = c ^ (((o >> 1) & 7) << 2);
        *(float4*)&Ws[o*128 + cs*4] = *(const float4*)&W[(o0+o)*Dz + c*4];
    }
    for (int idx = tid; idx < 32*32; idx += 256){
        int n = idx >> 5, c = idx & 31;
        *(float4*)&Xs[n*128 + c*4] = *(const float4*)&X[(n0+n)*Dz + c*4];
    }
    __syncthreads();

    int ol = tid & 31;
    int ng = tid >> 5;
    int r0 = ng * 4;
    int sw = (ol & 7) << 2;

    float a0x=0,a0y=0,a1x=0,a1y=0,a2x=0,a2y=0,a3x=0,a3y=0;
    #pragma unroll 8
    for (int c = 0; c < 32; c++){
        int cs = c ^ sw;
        float4 wa = *(float4*)&Ws[(2*ol  )*128 + cs*4];
        float4 wb = *(float4*)&Ws[(2*ol+1)*128 + cs*4];
        float4 x0 = *(float4*)&Xs[(r0+0)*128 + c*4];
        float4 x1 = *(float4*)&Xs[(r0+1)*128 + c*4];
        float4 x2 = *(float4*)&Xs[(r0+2)*128 + c*4];
        float4 x3 = *(float4*)&Xs[(r0+3)*128 + c*4];
        a0x += wa.x*x0.x + wa.y*x0.y + wa.z*x0.z + wa.w*x0.w;
        a0y += wb.x*x0.x + wb.y*x0.y + wb.z*x0.z + wb.w*x0.w;
        a1x += wa.x*x1.x + wa.y*x1.y + wa.z*x1.z + wa.w*x1.w;
        a1y += wb.x*x1.x + wb.y*x1.y + wb.z*x1.z + wb.w*x1.w;
        a2x += wa.x*x2.x + wa.y*x2.y + wa.z*x2.z + wa.w*x2.w;
        a2y += wb.x*x2.x + wb.y*x2.y + wb.z*x2.z + wb.w*x2.w;
        a3x += wa.x*x3.x + wa.y*x3.y + wa.z*x3.z + wa.w*x3.w;
        a3y += wb.x*x3.x + wb.y*x3.y + wb.z*x3.z + wb.w*x3.w;
    }
    float b0 = bias[o0 + 2*ol], b1 = bias[o0 + 2*ol + 1];
    float rx[4] = {a0x+b0, a1x+b0, a2x+b0, a3x+b0};
    float ry[4] = {a0y+b1, a1y+b1, a2y+b1, a3y+b1};

    if (which == 2){
        #pragma unroll
        for (int r = 0; r < 4; r++)
            *(float2*)&g_V[(n0+r0+r)*Dz + o0 + 2*ol] = make_float2(rx[r], ry[r]);
    } else {
        __half2* dst = which ? g_Kh : g_Qh;
        int d2 = (o0 >> 1) + ol;
        #pragma unroll
        for (int r = 0; r < 4; r++)
            dst[(n0+r0+r)*D2 + d2] = __floats2half2_rn(rx[r], ry[r]);
    }
}

// ---- scores + softmax fused ----
// CTA = (8 q, b), 256 thr. Warp qg owns q row; lane kl owns k=kl and k=kl+32
// of each 64-k tile. w·tanh accumulated via HFMA2 (fp16), flushed to f32
// every 8 d2. Logits live in registers; softmax per warp; no sP smem.
__global__ void k_scores(){
    __shared__ __half2 Ksh[D2][64];   // [d2][k ^ d2]  16KB
    __shared__ __half2 Qsh[8][D2];    // 2KB
    __shared__ __half2 swh[D2];       // 256B

    int b  = blockIdx.y;
    int q0 = blockIdx.x * 8;
    int tid = threadIdx.x;
    int kl = tid & 31, qg = tid >> 5;

    for (int idx = tid; idx < 8*D2; idx += 256){
        int q = idx >> 6, d2 = idx & 63;
        Qsh[q][d2] = g_Qh[(b*Lz + q0 + q)*D2 + d2];
    }
    if (tid < D2) swh[tid] = g_w2h[tid];
    float ball = g_b[0];

    const __half2* Kg = &g_Kh[(b*Lz)*D2];
    // fill mapping: f4 id f = tid + i*256 (i<4); row = f>>4, c4 = f&15
    int frow = tid >> 4, fc4 = tid & 15;

    float4 pre[4];
    #pragma unroll
    for (int i = 0; i < 4; i++)
        pre[i] = *(const float4*)&Kg[(frow + i*16)*D2 + fc4*4];

    float v[16];

    for (int kt = 0; kt < 8; kt++){
        __syncthreads();          // prev compute done before overwrite
        #pragma unroll
        for (int i = 0; i < 4; i++){
            int r = frow + i*16;
            const __half2* h = (const __half2*)&pre[i];
            #pragma unroll
            for (int j = 0; j < 4; j++){
                int d2 = fc4*4 + j;
                Ksh[d2][r ^ d2] = h[j];
            }
        }
        __syncthreads();
        if (kt < 7){
            #pragma unroll
            for (int i = 0; i < 4; i++)
                pre[i] = *(const float4*)&Kg[((kt+1)*64 + frow + i*16)*D2 + fc4*4];
        }

        float fa = 0.f, fb = 0.f;
        #pragma unroll
        for (int g = 0; g < 8; g++){
            __half2 ha = __floats2half2_rn(0.f, 0.f);
            __half2 hb = ha;
            #pragma unroll
            for (int u = 0; u < 8; u++){
                int d2 = g*8 + u;
                __half2 q2 = Qsh[qg][d2];
                __half2 w2 = swh[d2];
                __half2 ka = Ksh[d2][kl ^ d2];
                __half2 kb = Ksh[d2][(kl + 32) ^ d2];
                __half2 sa = __hadd2(q2, ka);
                __half2 sb = __hadd2(q2, kb);
                unsigned ta, tb;
                asm("tanh.approx.f16x2 %0, %1;" : "=r"(ta) : "r"(*(unsigned*)&sa));
                asm("tanh.approx.f16x2 %0, %1;" : "=r"(tb) : "r"(*(unsigned*)&sb));
                ha = __hfma2(w2, *(__half2*)&ta, ha);
                hb = __hfma2(w2, *(__half2*)&tb, hb);
            }
            float2 xa = __half22float2(ha);
            float2 xb = __half22float2(hb);
            fa += xa.x + xa.y;
            fb += xb.x + xb.y;
        }
        v[2*kt]     = fa + ball;
        v[2*kt + 1] = fb + ball;
    }

    // softmax of warp's q row directly from registers
    float m = -1e30f;
    #pragma unroll
    for (int j = 0; j < 16; j++) m = fmaxf(m, v[j]);
    #pragma unroll
    for (int s = 16; s; s >>= 1) m = fmaxf(m, __shfl_xor_sync(~0u, m, s));
    float ssum = 0.f;
    #pragma unroll
    for (int j = 0; j < 16; j++){ v[j] = __expf(v[j] - m); ssum += v[j]; }
    #pragma unroll
    for (int s = 16; s; s >>= 1) ssum += __shfl_xor_sync(~0u, ssum, s);
    float inv = 1.f / ssum;
    float* dst = &g_P[(b*Lz + q0 + qg)*Lz];
    #pragma unroll
    for (int kt = 0; kt < 8; kt++){
        dst[kt*64 + kl]      = v[2*kt]     * inv;
        dst[kt*64 + 32 + kl] = v[2*kt + 1] * inv;
    }
}

// ---- out[b,q,:] = sum_k attn[b,q,k] * V[b,k,:] ----
// CTA = 32 q, 256 thr, 8 warps; warp owns 4 q, lane owns 4 d.
// k tiled by 32, double-buffered via cp.async; attn via broadcast LDS.
__global__ void k_av(float* __restrict__ Out){
    __shared__ __align__(16) float Vs[2][32][Dz];   // 2 x 16KB
    __shared__ __align__(16) float aP[2][32][32];   // 2 x 4KB
    int b  = blockIdx.y;
    int q0 = blockIdx.x * 32;
    int tid = threadIdx.x;
    int lane = tid & 31, w = tid >> 5;
    int qb = w * 4;

    const float* Vg = &g_V[(b*Lz)*Dz];
    const float* Pg = &g_P[(b*Lz + q0)*Lz];

    int vrow0 = tid >> 5, vcol = (tid & 31) * 4;
    int prow = tid >> 3, pcol = (tid & 7) * 4;

    unsigned sV0 = (unsigned)__cvta_generic_to_shared(&Vs[0][0][0]) + tid*16u;
    unsigned sV1 = (unsigned)__cvta_generic_to_shared(&Vs[1][0][0]) + tid*16u;
    unsigned sA0 = (unsigned)__cvta_generic_to_shared(&aP[0][prow][pcol]);
    unsigned sA1 = (unsigned)__cvta_generic_to_shared(&aP[1][prow][pcol]);

    {
        #pragma unroll
        for (int i = 0; i < 4; i++)
            cp16(sV0 + i*4096u, &Vg[(vrow0 + i*8)*Dz + vcol]);
        cp16(sA0, &Pg[prow*Lz + pcol]);
        asm volatile("cp.async.commit_group;");
    }

    float4 acc0 = make_float4(0.f,0.f,0.f,0.f);
    float4 acc1 = acc0, acc2 = acc0, acc3 = acc0;

    for (int kt = 0; kt < 16; kt++){
        int buf = kt & 1;
        if (kt + 1 < 16){
            int k0 = (kt + 1) * 32;
            unsigned sV = buf ? sV0 : sV1;
            unsigned sA = buf ? sA0 : sA1;
            #pragma unroll
            for (int i = 0; i < 4; i++)
                cp16(sV + i*4096u, &Vg[(k0 + vrow0 + i*8)*Dz + vcol]);
            cp16(sA, &Pg[prow*Lz + k0 + pcol]);
            asm volatile("cp.async.commit_group;");
            asm volatile("cp.async.wait_group 1;");
        } else {
            asm volatile("cp.async.wait_group 0;");
        }
        __syncthreads();

        #pragma unroll 8
        for (int j = 0; j < 32; j++){
            float4 v = *(const float4*)&Vs[buf][j][lane*4];
            float p0 = aP[buf][qb+0][j];
            float p1 = aP[buf][qb+1][j];
            float p2 = aP[buf][qb+2][j];
            float p3 = aP[buf][qb+3][j];
            acc0.x += p0*v.x; acc0.y += p0*v.y; acc0.z += p0*v.z; acc0.w += p0*v.w;
            acc1.x += p1*v.x; acc1.y += p1*v.y; acc1.z += p1*v.z; acc1.w += p1*v.w;
            acc2.x += p2*v.x; acc2.y += p2*v.y; acc2.z += p2*v.z; acc2.w += p2*v.w;
            acc3.x += p3*v.x; acc3.y += p3*v.y; acc3.z += p3*v.z; acc3.w += p3*v.w;
        }
        __syncthreads();
    }
    *(float4*)&Out[(b*Lz + q0 + qb + 0)*Dz + lane*4] = acc0;
    *(float4*)&Out[(b*Lz + q0 + qb + 1)*Dz + lane*4] = acc1;
    *(float4*)&Out[(b*Lz + q0 + qb + 2)*Dz + lane*4] = acc2;
    *(float4*)&Out[(b*Lz + q0 + qb + 3)*Dz + lane*4] = acc3;
}

extern "C" void kernel_launch(void* const* d_in, const int* in_sizes, int n_in,
                              void* d_out, int out_size){
    const float* query = (const float*)d_in[0];
    const float* key_  = (const float*)d_in[1];
    const float* value = (const float*)d_in[2];
    const float* Wq = (const float*)d_in[3];
    const float* bq = (const float*)d_in[4];
    const float* Wk = (const float*)d_in[5];
    const float* bk = (const float*)d_in[6];
    const float* Wv = (const float*)d_in[7];
    const float* bv = (const float*)d_in[8];
    const float* wd = (const float*)d_in[9];
    const float* bd = (const float*)d_in[10];
    const float* ws = (const float*)d_in[11];
    const float* bs = (const float*)d_in[12];
    const float* wt = (const float*)d_in[13];
    const float* bt = (const float*)d_in[14];
    float* out = (float*)d_out;

    k_prep<<<1, 64>>>(wd, bd, ws, bs, wt, bt);
    k_proj<<<dim3(Bz*Lz/32, 2, 3), 256>>>(query, key_, value,
                                          Wq, bq, Wk, bk, Wv, bv);
    k_scores<<<dim3(Lz/8, Bz), 256>>>();
    k_av<<<dim3(Lz/32, Bz), 256>>>(out);
}

// round 10
// speedup vs baseline: 1.3864x; 1.0316x over previous
#include <cuda_runtime.h>
#include <cuda_fp16.h>

#define Bz 8
#define Lz 512
#define Dz 128
#define D2 64   // Dz/2 half2 pairs

// ---- scratch (device globals; no allocation allowed) ----
__device__ __half2 g_Qh[Bz*Lz*D2];
__device__ __half2 g_Kh[Bz*Lz*D2];
__device__ float   g_V [Bz*Lz*Dz];
__device__ float   g_P [Bz*Lz*Lz];   // attn probabilities
__device__ __half2 g_w2h[D2];        // combined score weights (half2)
__device__ float   g_b[1];

__device__ __forceinline__ void cp16(unsigned smem, const void* g){
    asm volatile("cp.async.ca.shared.global [%0], [%1], 16;" :: "r"(smem), "l"(g));
}

// ---- combine the three score heads + 1/sqrt(D) into one weight vector ----
__global__ void k_prep(const float* wd, const float* bd, const float* ws,
                       const float* bs, const float* wt, const float* bt){
    int i = threadIdx.x;     // 64 threads
    if (i < D2){
        float base = 0.08838834764831845f; // 1/sqrt(128)
        float wx = base + wd[2*i]   + ws[2*i]   + wt[2*i];
        float wy = base + wd[2*i+1] + ws[2*i+1] + wt[2*i+1];
        g_w2h[i] = __floats2half2_rn(wx, wy);
    }
    if (i == 0) g_b[0] = bd[0] + bs[0] + bt[0];
}

// ---- fused QKV projection: Out[n,o] = sum_i X[n,i]*W[o,i] + b[o] ----
// CTA 64n x 64o, 256 thr, thread = 4n x 4o (o cols: 2tc,2tc+1,2tc+32,2tc+33).
// K dim split in two 64-halves staged in smem. 8 LDS.128 per 64 FFMA.
__global__ void k_proj(const float* __restrict__ Xq, const float* __restrict__ Xk,
                       const float* __restrict__ Xv,
                       const float* __restrict__ Wq, const float* __restrict__ bq,
                       const float* __restrict__ Wk, const float* __restrict__ bk,
                       const float* __restrict__ Wv, const float* __restrict__ bv){
    __shared__ __align__(16) float Ws[64*68];    // stride 68: conflict-light
    __shared__ __align__(16) float Xs[64*68];
    int which = blockIdx.z;
    const float* X    = (which==0) ? Xq : (which==1) ? Xk : Xv;
    const float* W    = (which==0) ? Wq : (which==1) ? Wk : Wv;
    const float* bias = (which==0) ? bq : (which==1) ? bk : bv;

    int n0 = blockIdx.x * 64;
    int o0 = blockIdx.y * 64;
    int tid = threadIdx.x;
    int tr = tid >> 4;        // 0..15 -> n rows 4tr..4tr+3
    int tc = tid & 15;        // o cols 2tc, 2tc+1, 2tc+32, 2tc+33

    float acc[4][4];
    #pragma unroll
    for (int r = 0; r < 4; r++)
        #pragma unroll
        for (int j = 0; j < 4; j++) acc[r][j] = 0.f;

    #pragma unroll
    for (int kh = 0; kh < 2; kh++){
        __syncthreads();
        for (int idx = tid; idx < 1024; idx += 256){
            int r = idx >> 4, c = idx & 15;
            *(float4*)&Ws[r*68 + c*4] = *(const float4*)&W[(o0+r)*Dz + kh*64 + c*4];
            *(float4*)&Xs[r*68 + c*4] = *(const float4*)&X[(n0+r)*Dz + kh*64 + c*4];
        }
        __syncthreads();
        #pragma unroll 4
        for (int c = 0; c < 16; c++){
            float4 w0 = *(float4*)&Ws[(2*tc   )*68 + c*4];
            float4 w1 = *(float4*)&Ws[(2*tc+ 1)*68 + c*4];
            float4 w2 = *(float4*)&Ws[(2*tc+32)*68 + c*4];
            float4 w3 = *(float4*)&Ws[(2*tc+33)*68 + c*4];
            #pragma unroll
            for (int r = 0; r < 4; r++){
                float4 x = *(float4*)&Xs[(4*tr+r)*68 + c*4];
                acc[r][0] += w0.x*x.x + w0.y*x.y + w0.z*x.z + w0.w*x.w;
                acc[r][1] += w1.x*x.x + w1.y*x.y + w1.z*x.z + w1.w*x.w;
                acc[r][2] += w2.x*x.x + w2.y*x.y + w2.z*x.z + w2.w*x.w;
                acc[r][3] += w3.x*x.x + w3.y*x.y + w3.z*x.z + w3.w*x.w;
            }
        }
    }

    float b0 = bias[o0 + 2*tc],      b1 = bias[o0 + 2*tc + 1];
    float b2 = bias[o0 + 2*tc + 32], b3 = bias[o0 + 2*tc + 33];

    if (which == 2){
        #pragma unroll
        for (int r = 0; r < 4; r++){
            int n = n0 + 4*tr + r;
            *(float2*)&g_V[n*Dz + o0 + 2*tc]      = make_float2(acc[r][0]+b0, acc[r][1]+b1);
            *(float2*)&g_V[n*Dz + o0 + 2*tc + 32] = make_float2(acc[r][2]+b2, acc[r][3]+b3);
        }
    } else {
        __half2* dst = which ? g_Kh : g_Qh;
        int d2a = (o0 >> 1) + tc;
        int d2b = d2a + 16;
        #pragma unroll
        for (int r = 0; r < 4; r++){
            int n = n0 + 4*tr + r;
            dst[n*D2 + d2a] = __floats2half2_rn(acc[r][0]+b0, acc[r][1]+b1);
            dst[n*D2 + d2b] = __floats2half2_rn(acc[r][2]+b2, acc[r][3]+b3);
        }
    }
}

// ---- scores + softmax fused ----
// CTA = (16 q, b), 256 thr. Warp w owns q rows 2w,2w+1; lane kl owns k=kl,
// k=kl+32 per 64-k tile. ka/kb LDS amortized over 2 q rows. fp16 HFMA2
// accumulation flushed to f32 every 8 d2; logits in regs; warp softmax.
__global__ void k_scores(){
    __shared__ __half2 Ksh[D2][64];   // [d2][k ^ d2]  16KB
    __shared__ __half2 Qsh[16][D2];   // 4KB
    __shared__ __half2 swh[D2];       // 256B

    int b  = blockIdx.y;
    int q0 = blockIdx.x * 16;
    int tid = threadIdx.x;
    int kl = tid & 31, w = tid >> 5;

    for (int idx = tid; idx < 16*D2; idx += 256){
        int q = idx >> 6, d2 = idx & 63;
        Qsh[q][d2] = g_Qh[(b*Lz + q0 + q)*D2 + d2];
    }
    if (tid < D2) swh[tid] = g_w2h[tid];
    float ball = g_b[0];

    const __half2* Kg = &g_Kh[(b*Lz)*D2];
    int frow = tid >> 4, fc4 = tid & 15;

    float4 pre[4];
    #pragma unroll
    for (int i = 0; i < 4; i++)
        pre[i] = *(const float4*)&Kg[(frow + i*16)*D2 + fc4*4];

    float va[16], vb[16];   // logits: q row 2w / 2w+1

    #pragma unroll
    for (int kt = 0; kt < 8; kt++){
        __syncthreads();
        #pragma unroll
        for (int i = 0; i < 4; i++){
            int r = frow + i*16;
            const __half2* h = (const __half2*)&pre[i];
            #pragma unroll
            for (int j = 0; j < 4; j++){
                int d2 = fc4*4 + j;
                Ksh[d2][r ^ d2] = h[j];
            }
        }
        __syncthreads();
        if (kt < 7){
            #pragma unroll
            for (int i = 0; i < 4; i++)
                pre[i] = *(const float4*)&Kg[((kt+1)*64 + frow + i*16)*D2 + fc4*4];
        }

        float fa0 = 0.f, fb0 = 0.f, fa1 = 0.f, fb1 = 0.f;
        #pragma unroll
        for (int g = 0; g < 8; g++){
            __half2 z = __floats2half2_rn(0.f, 0.f);
            __half2 ha0 = z, hb0 = z, ha1 = z, hb1 = z;
            #pragma unroll
            for (int u = 0; u < 8; u++){
                int d2 = g*8 + u;
                __half2 qa = Qsh[2*w  ][d2];
                __half2 qb = Qsh[2*w+1][d2];
                __half2 w2 = swh[d2];
                __half2 ka = Ksh[d2][kl ^ d2];
                __half2 kb = Ksh[d2][(kl + 32) ^ d2];
                __half2 s0 = __hadd2(qa, ka);
                __half2 s1 = __hadd2(qa, kb);
                __half2 s2 = __hadd2(qb, ka);
                __half2 s3 = __hadd2(qb, kb);
                unsigned t0, t1, t2, t3;
                asm("tanh.approx.f16x2 %0, %1;" : "=r"(t0) : "r"(*(unsigned*)&s0));
                asm("tanh.approx.f16x2 %0, %1;" : "=r"(t1) : "r"(*(unsigned*)&s1));
                asm("tanh.approx.f16x2 %0, %1;" : "=r"(t2) : "r"(*(unsigned*)&s2));
                asm("tanh.approx.f16x2 %0, %1;" : "=r"(t3) : "r"(*(unsigned*)&s3));
                ha0 = __hfma2(w2, *(__half2*)&t0, ha0);
                hb0 = __hfma2(w2, *(__half2*)&t1, hb0);
                ha1 = __hfma2(w2, *(__half2*)&t2, ha1);
                hb1 = __hfma2(w2, *(__half2*)&t3, hb1);
            }
            float2 x0 = __half22float2(ha0);
            float2 x1 = __half22float2(hb0);
            float2 x2 = __half22float2(ha1);
            float2 x3 = __half22float2(hb1);
            fa0 += x0.x + x0.y;
            fb0 += x1.x + x1.y;
            fa1 += x2.x + x2.y;
            fb1 += x3.x + x3.y;
        }
        va[2*kt] = fa0 + ball; va[2*kt+1] = fb0 + ball;
        vb[2*kt] = fa1 + ball; vb[2*kt+1] = fb1 + ball;
    }

    // two independent warp softmaxes (rows 2w, 2w+1) from registers
    float ma = -1e30f, mb = -1e30f;
    #pragma unroll
    for (int j = 0; j < 16; j++){ ma = fmaxf(ma, va[j]); mb = fmaxf(mb, vb[j]); }
    #pragma unroll
    for (int s = 16; s; s >>= 1){
        ma = fmaxf(ma, __shfl_xor_sync(~0u, ma, s));
        mb = fmaxf(mb, __shfl_xor_sync(~0u, mb, s));
    }
    float sa = 0.f, sb = 0.f;
    #pragma unroll
    for (int j = 0; j < 16; j++){
        va[j] = __expf(va[j] - ma); sa += va[j];
        vb[j] = __expf(vb[j] - mb); sb += vb[j];
    }
    #pragma unroll
    for (int s = 16; s; s >>= 1){
        sa += __shfl_xor_sync(~0u, sa, s);
        sb += __shfl_xor_sync(~0u, sb, s);
    }
    float ia = 1.f / sa, ib = 1.f / sb;
    float* da = &g_P[(b*Lz + q0 + 2*w    )*Lz];
    float* db = &g_P[(b*Lz + q0 + 2*w + 1)*Lz];
    #pragma unroll
    for (int kt = 0; kt < 8; kt++){
        da[kt*64 + kl]      = va[2*kt]   * ia;
        da[kt*64 + 32 + kl] = va[2*kt+1] * ia;
        db[kt*64 + kl]      = vb[2*kt]   * ib;
        db[kt*64 + 32 + kl] = vb[2*kt+1] * ib;
    }
}

// ---- out[b,q,:] = sum_k attn[b,q,k] * V[b,k,:] ---- (unchanged)
__global__ void k_av(float* __restrict__ Out){
    __shared__ __align__(16) float Vs[2][32][Dz];   // 2 x 16KB
    __shared__ __align__(16) float aP[2][32][32];   // 2 x 4KB
    int b  = blockIdx.y;
    int q0 = blockIdx.x * 32;
    int tid = threadIdx.x;
    int lane = tid & 31, w = tid >> 5;
    int qb = w * 4;

    const float* Vg = &g_V[(b*Lz)*Dz];
    const float* Pg = &g_P[(b*Lz + q0)*Lz];

    int vrow0 = tid >> 5, vcol = (tid & 31) * 4;
    int prow = tid >> 3, pcol = (tid & 7) * 4;

    unsigned sV0 = (unsigned)__cvta_generic_to_shared(&Vs[0][0][0]) + tid*16u;
    unsigned sV1 = (unsigned)__cvta_generic_to_shared(&Vs[1][0][0]) + tid*16u;
    unsigned sA0 = (unsigned)__cvta_generic_to_shared(&aP[0][prow][pcol]);
    unsigned sA1 = (unsigned)__cvta_generic_to_shared(&aP[1][prow][pcol]);

    {
        #pragma unroll
        for (int i = 0; i < 4; i++)
            cp16(sV0 + i*4096u, &Vg[(vrow0 + i*8)*Dz + vcol]);
        cp16(sA0, &Pg[prow*Lz + pcol]);
        asm volatile("cp.async.commit_group;");
    }

    float4 acc0 = make_float4(0.f,0.f,0.f,0.f);
    float4 acc1 = acc0, acc2 = acc0, acc3 = acc0;

    for (int kt = 0; kt < 16; kt++){
        int buf = kt & 1;
        if (kt + 1 < 16){
            int k0 = (kt + 1) * 32;
            unsigned sV = buf ? sV0 : sV1;
            unsigned sA = buf ? sA0 : sA1;
            #pragma unroll
            for (int i = 0; i < 4; i++)
                cp16(sV + i*4096u, &Vg[(k0 + vrow0 + i*8)*Dz + vcol]);
            cp16(sA, &Pg[prow*Lz + k0 + pcol]);
            asm volatile("cp.async.commit_group;");
            asm volatile("cp.async.wait_group 1;");
        } else {
            asm volatile("cp.async.wait_group 0;");
        }
        __syncthreads();

        #pragma unroll 8
        for (int j = 0; j < 32; j++){
            float4 v = *(const float4*)&Vs[buf][j][lane*4];
            float p0 = aP[buf][qb+0][j];
            float p1 = aP[buf][qb+1][j];
            float p2 = aP[buf][qb+2][j];
            float p3 = aP[buf][qb+3][j];
            acc0.x += p0*v.x; acc0.y += p0*v.y; acc0.z += p0*v.z; acc0.w += p0*v.w;
            acc1.x += p1*v.x; acc1.y += p1*v.y; acc1.z += p1*v.z; acc1.w += p1*v.w;
            acc2.x += p2*v.x; acc2.y += p2*v.y; acc2.z += p2*v.z; acc2.w += p2*v.w;
            acc3.x += p3*v.x; acc3.y += p3*v.y; acc3.z += p3*v.z; acc3.w += p3*v.w;
        }
        __syncthreads();
    }
    *(float4*)&Out[(b*Lz + q0 + qb + 0)*Dz + lane*4] = acc0;
    *(float4*)&Out[(b*Lz + q0 + qb + 1)*Dz + lane*4] = acc1;
    *(float4*)&Out[(b*Lz + q0 + qb + 2)*Dz + lane*4] = acc2;
    *(float4*)&Out[(b*Lz + q0 + qb + 3)*Dz + lane*4] = acc3;
}

extern "C" void kernel_launch(void* const* d_in, const int* in_sizes, int n_in,
                              void* d_out, int out_size){
    const float* query = (const float*)d_in[0];
    const float* key_  = (const float*)d_in[1];
    const float* value = (const float*)d_in[2];
    const float* Wq = (const float*)d_in[3];
    const float* bq = (const float*)d_in[4];
    const float* Wk = (const float*)d_in[5];
    const float* bk = (const float*)d_in[6];
    const float* Wv = (const float*)d_in[7];
    const float* bv = (const float*)d_in[8];
    const float* wd = (const float*)d_in[9];
    const float* bd = (const float*)d_in[10];
    const float* ws = (const float*)d_in[11];
    const float* bs = (const float*)d_in[12];
    const float* wt = (const float*)d_in[13];
    const float* bt = (const float*)d_in[14];
    float* out = (float*)d_out;

    k_prep<<<1, 64>>>(wd, bd, ws, bs, wt, bt);
    k_proj<<<dim3(Bz*Lz/64, 2, 3), 256>>>(query, key_, value,
                                          Wq, bq, Wk, bk, Wv, bv);
    k_scores<<<dim3(Lz/16, Bz), 256>>>();
    k_av<<<dim3(Lz/32, Bz), 256>>>(out);
}

// round 12
// speedup vs baseline: 1.5850x; 1.1432x over previous
#include <cuda_runtime.h>
#include <cuda_fp16.h>

#define Bz 8
#define Lz 512
#define Dz 128
#define D2 64   // Dz/2 half2 pairs

// ---- scratch (device globals; no allocation allowed) ----
__device__ __half2 g_Qh[Bz*Lz*D2];
__device__ __half2 g_Kh[Bz*Lz*D2];
__device__ float   g_V [Bz*Lz*Dz];
__device__ float   g_P [Bz*Lz*Lz];   // attn probabilities
__device__ __half2 g_w2h[D2];        // combined score weights (half2)
__device__ float   g_b[1];

__device__ __forceinline__ void cp16(unsigned smem, const void* g){
    asm volatile("cp.async.ca.shared.global [%0], [%1], 16;" :: "r"(smem), "l"(g));
}

// ---- projection tile body: Out[n,o] = sum_i X[n,i]*W[o,i] + b[o] ----
// 64n x 64o tile, 256 thr, thread = 4n x 4o. K split in two 64-halves.
// which: 0 -> g_Qh (half2), 1 -> g_Kh (half2), 2 -> g_V (fp32)
__device__ __forceinline__ void proj_tile(
        const float* __restrict__ X, const float* __restrict__ W,
        const float* __restrict__ bias, int which, int n0, int o0,
        float* Ws, float* Xs, int tid){
    int tr = tid >> 4;        // 0..15 -> n rows 4tr..4tr+3
    int tc = tid & 15;        // o cols 2tc, 2tc+1, 2tc+32, 2tc+33

    float acc[4][4];
    #pragma unroll
    for (int r = 0; r < 4; r++)
        #pragma unroll
        for (int j = 0; j < 4; j++) acc[r][j] = 0.f;

    #pragma unroll
    for (int kh = 0; kh < 2; kh++){
        __syncthreads();
        for (int idx = tid; idx < 1024; idx += 256){
            int r = idx >> 4, c = idx & 15;
            *(float4*)&Ws[r*68 + c*4] = *(const float4*)&W[(o0+r)*Dz + kh*64 + c*4];
            *(float4*)&Xs[r*68 + c*4] = *(const float4*)&X[(n0+r)*Dz + kh*64 + c*4];
        }
        __syncthreads();
        #pragma unroll 4
        for (int c = 0; c < 16; c++){
            float4 w0 = *(float4*)&Ws[(2*tc   )*68 + c*4];
            float4 w1 = *(float4*)&Ws[(2*tc+ 1)*68 + c*4];
            float4 w2 = *(float4*)&Ws[(2*tc+32)*68 + c*4];
            float4 w3 = *(float4*)&Ws[(2*tc+33)*68 + c*4];
            #pragma unroll
            for (int r = 0; r < 4; r++){
                float4 x = *(float4*)&Xs[(4*tr+r)*68 + c*4];
                acc[r][0] += w0.x*x.x + w0.y*x.y + w0.z*x.z + w0.w*x.w;
                acc[r][1] += w1.x*x.x + w1.y*x.y + w1.z*x.z + w1.w*x.w;
                acc[r][2] += w2.x*x.x + w2.y*x.y + w2.z*x.z + w2.w*x.w;
                acc[r][3] += w3.x*x.x + w3.y*x.y + w3.z*x.z + w3.w*x.w;
            }
        }
    }

    float b0 = bias[o0 + 2*tc],      b1 = bias[o0 + 2*tc + 1];
    float b2 = bias[o0 + 2*tc + 32], b3 = bias[o0 + 2*tc + 33];

    if (which == 2){
        #pragma unroll
        for (int r = 0; r < 4; r++){
            int n = n0 + 4*tr + r;
            *(float2*)&g_V[n*Dz + o0 + 2*tc]      = make_float2(acc[r][0]+b0, acc[r][1]+b1);
            *(float2*)&g_V[n*Dz + o0 + 2*tc + 32] = make_float2(acc[r][2]+b2, acc[r][3]+b3);
        }
    } else {
        __half2* dst = which ? g_Kh : g_Qh;
        int d2a = (o0 >> 1) + tc;
        int d2b = d2a + 16;
        #pragma unroll
        for (int r = 0; r < 4; r++){
            int n = n0 + 4*tr + r;
            dst[n*D2 + d2a] = __floats2half2_rn(acc[r][0]+b0, acc[r][1]+b1);
            dst[n*D2 + d2b] = __floats2half2_rn(acc[r][2]+b2, acc[r][3]+b3);
        }
    }
}

// ---- launch 1: Q-proj + K-proj + prep (1-D grid 257) ----
__global__ void __launch_bounds__(256, 2)
k_qk_prep(const float* __restrict__ Xq, const float* __restrict__ Xk,
          const float* __restrict__ Wq, const float* __restrict__ bq,
          const float* __restrict__ Wk, const float* __restrict__ bk,
          const float* wd, const float* bd, const float* ws,
          const float* bs, const float* wt, const float* bt){
    __shared__ __align__(16) float sm[2*64*68];
    int id = blockIdx.x;
    int tid = threadIdx.x;
    if (id == 256){                       // prep block
        if (tid < D2){
            float base = 0.08838834764831845f; // 1/sqrt(128)
            float wx = base + wd[2*tid]   + ws[2*tid]   + wt[2*tid];
            float wy = base + wd[2*tid+1] + ws[2*tid+1] + wt[2*tid+1];
            g_w2h[tid] = __floats2half2_rn(wx, wy);
        }
        if (tid == 0) g_b[0] = bd[0] + bs[0] + bt[0];
        return;
    }
    int which = id >> 7;                  // 0 = Q, 1 = K
    int rem = id & 127;
    int n0 = (rem & 63) * 64;
    int o0 = (rem >> 6) * 64;
    proj_tile(which ? Xk : Xq, which ? Wk : Wq, which ? bk : bq,
              which, n0, o0, sm, sm + 64*68, tid);
}

// ---- launch 2: scores+softmax (blocks 0..255) + V-proj (blocks 256..383) ----
// scores CTA = (16 q, b): warp w owns q rows 2w,2w+1; lane kl owns k=kl,kl+32
// per 64-k tile. HFMA2 accumulation flushed to f32 every 8 d2; logits in regs.
__global__ void __launch_bounds__(256, 2)
k_scores_v(const float* __restrict__ Xv, const float* __restrict__ Wv,
           const float* __restrict__ bv){
    __shared__ __align__(16) float sm[2*64*68];   // 34816B union
    int id = blockIdx.x;
    int tid = threadIdx.x;

    if (id >= 256){                       // V projection (FMA-bound, overlaps MUFU)
        int pid = id - 256;
        int n0 = (pid & 63) * 64;
        int o0 = (pid >> 6) * 64;
        proj_tile(Xv, Wv, bv, 2, n0, o0, sm, sm + 64*68, tid);
        return;
    }

    __half2* Ksh = (__half2*)sm;                  // [D2][64] 16KB
    __half2* Qsh = (__half2*)(sm + 4096);         // [16][D2] 4KB
    __half2* swh = (__half2*)(sm + 4096 + 1024);  // [D2] 256B

    int b  = id >> 5;
    int q0 = (id & 31) * 16;
    int kl = tid & 31, w = tid >> 5;

    for (int idx = tid; idx < 16*D2; idx += 256){
        int q = idx >> 6, d2 = idx & 63;
        Qsh[q*D2 + d2] = g_Qh[(b*Lz + q0 + q)*D2 + d2];
    }
    if (tid < D2) swh[tid] = g_w2h[tid];
    float ball = g_b[0];

    const __half2* Kg = &g_Kh[(b*Lz)*D2];
    int frow = tid >> 4, fc4 = tid & 15;

    float4 pre[4];
    #pragma unroll
    for (int i = 0; i < 4; i++)
        pre[i] = *(const float4*)&Kg[(frow + i*16)*D2 + fc4*4];

    float va[16], vb[16];

    #pragma unroll
    for (int kt = 0; kt < 8; kt++){
        __syncthreads();
        #pragma unroll
        for (int i = 0; i < 4; i++){
            int r = frow + i*16;
            const __half2* h = (const __half2*)&pre[i];
            #pragma unroll
            for (int j = 0; j < 4; j++){
                int d2 = fc4*4 + j;
                Ksh[d2*64 + (r ^ d2)] = h[j];
            }
        }
        __syncthreads();
        if (kt < 7){
            #pragma unroll
            for (int i = 0; i < 4; i++)
                pre[i] = *(const float4*)&Kg[((kt+1)*64 + frow + i*16)*D2 + fc4*4];
        }

        float fa0 = 0.f, fb0 = 0.f, fa1 = 0.f, fb1 = 0.f;
        #pragma unroll
        for (int g = 0; g < 8; g++){
            __half2 z = __floats2half2_rn(0.f, 0.f);
            __half2 ha0 = z, hb0 = z, ha1 = z, hb1 = z;
            #pragma unroll
            for (int u = 0; u < 8; u++){
                int d2 = g*8 + u;
                __half2 qa = Qsh[(2*w  )*D2 + d2];
                __half2 qb = Qsh[(2*w+1)*D2 + d2];
                __half2 w2 = swh[d2];
                __half2 ka = Ksh[d2*64 + (kl ^ d2)];
                __half2 kb = Ksh[d2*64 + ((kl + 32) ^ d2)];
                __half2 s0 = __hadd2(qa, ka);
                __half2 s1 = __hadd2(qa, kb);
                __half2 s2 = __hadd2(qb, ka);
                __half2 s3 = __hadd2(qb, kb);
                unsigned t0, t1, t2, t3;
                asm("tanh.approx.f16x2 %0, %1;" : "=r"(t0) : "r"(*(unsigned*)&s0));
                asm("tanh.approx.f16x2 %0, %1;" : "=r"(t1) : "r"(*(unsigned*)&s1));
                asm("tanh.approx.f16x2 %0, %1;" : "=r"(t2) : "r"(*(unsigned*)&s2));
                asm("tanh.approx.f16x2 %0, %1;" : "=r"(t3) : "r"(*(unsigned*)&s3));
                ha0 = __hfma2(w2, *(__half2*)&t0, ha0);
                hb0 = __hfma2(w2, *(__half2*)&t1, hb0);
                ha1 = __hfma2(w2, *(__half2*)&t2, ha1);
                hb1 = __hfma2(w2, *(__half2*)&t3, hb1);
            }
            float2 x0 = __half22float2(ha0);
            float2 x1 = __half22float2(hb0);
            float2 x2 = __half22float2(ha1);
            float2 x3 = __half22float2(hb1);
            fa0 += x0.x + x0.y;
            fb0 += x1.x + x1.y;
            fa1 += x2.x + x2.y;
            fb1 += x3.x + x3.y;
        }
        va[2*kt] = fa0 + ball; va[2*kt+1] = fb0 + ball;
        vb[2*kt] = fa1 + ball; vb[2*kt+1] = fb1 + ball;
    }

    float ma = -1e30f, mb = -1e30f;
    #pragma unroll
    for (int j = 0; j < 16; j++){ ma = fmaxf(ma, va[j]); mb = fmaxf(mb, vb[j]); }
    #pragma unroll
    for (int s = 16; s; s >>= 1){
        ma = fmaxf(ma, __shfl_xor_sync(~0u, ma, s));
        mb = fmaxf(mb, __shfl_xor_sync(~0u, mb, s));
    }
    float sa = 0.f, sb = 0.f;
    #pragma unroll
    for (int j = 0; j < 16; j++){
        va[j] = __expf(va[j] - ma); sa += va[j];
        vb[j] = __expf(vb[j] - mb); sb += vb[j];
    }
    #pragma unroll
    for (int s = 16; s; s >>= 1){
        sa += __shfl_xor_sync(~0u, sa, s);
        sb += __shfl_xor_sync(~0u, sb, s);
    }
    float ia = 1.f / sa, ib = 1.f / sb;
    float* da = &g_P[(b*Lz + q0 + 2*w    )*Lz];
    float* db = &g_P[(b*Lz + q0 + 2*w + 1)*Lz];
    #pragma unroll
    for (int kt = 0; kt < 8; kt++){
        da[kt*64 + kl]      = va[2*kt]   * ia;
        da[kt*64 + 32 + kl] = va[2*kt+1] * ia;
        db[kt*64 + kl]      = vb[2*kt]   * ib;
        db[kt*64 + 32 + kl] = vb[2*kt+1] * ib;
    }
}

// ---- launch 3: out[b,q,:] = sum_k attn[b,q,k] * V[b,k,:] ---- (unchanged)
__global__ void k_av(float* __restrict__ Out){
    __shared__ __align__(16) float Vs[2][32][Dz];   // 2 x 16KB
    __shared__ __align__(16) float aP[2][32][32];   // 2 x 4KB
    int b  = blockIdx.y;
    int q0 = blockIdx.x * 32;
    int tid = threadIdx.x;
    int lane = tid & 31, w = tid >> 5;
    int qb = w * 4;

    const float* Vg = &g_V[(b*Lz)*Dz];
    const float* Pg = &g_P[(b*Lz + q0)*Lz];

    int vrow0 = tid >> 5, vcol = (tid & 31) * 4;
    int prow = tid >> 3, pcol = (tid & 7) * 4;

    unsigned sV0 = (unsigned)__cvta_generic_to_shared(&Vs[0][0][0]) + tid*16u;
    unsigned sV1 = (unsigned)__cvta_generic_to_shared(&Vs[1][0][0]) + tid*16u;
    unsigned sA0 = (unsigned)__cvta_generic_to_shared(&aP[0][prow][pcol]);
    unsigned sA1 = (unsigned)__cvta_generic_to_shared(&aP[1][prow][pcol]);

    {
        #pragma unroll
        for (int i = 0; i < 4; i++)
            cp16(sV0 + i*4096u, &Vg[(vrow0 + i*8)*Dz + vcol]);
        cp16(sA0, &Pg[prow*Lz + pcol]);
        asm volatile("cp.async.commit_group;");
    }

    float4 acc0 = make_float4(0.f,0.f,0.f,0.f);
    float4 acc1 = acc0, acc2 = acc0, acc3 = acc0;

    for (int kt = 0; kt < 16; kt++){
        int buf = kt & 1;
        if (kt + 1 < 16){
            int k0 = (kt + 1) * 32;
            unsigned sV = buf ? sV0 : sV1;
            unsigned sA = buf ? sA0 : sA1;
            #pragma unroll
            for (int i = 0; i < 4; i++)
                cp16(sV + i*4096u, &Vg[(k0 + vrow0 + i*8)*Dz + vcol]);
            cp16(sA, &Pg[prow*Lz + k0 + pcol]);
            asm volatile("cp.async.commit_group;");
            asm volatile("cp.async.wait_group 1;");
        } else {
            asm volatile("cp.async.wait_group 0;");
        }
        __syncthreads();

        #pragma unroll 8
        for (int j = 0; j < 32; j++){
            float4 v = *(const float4*)&Vs[buf][j][lane*4];
            float p0 = aP[buf][qb+0][j];
            float p1 = aP[buf][qb+1][j];
            float p2 = aP[buf][qb+2][j];
            float p3 = aP[buf][qb+3][j];
            acc0.x += p0*v.x; acc0.y += p0*v.y; acc0.z += p0*v.z; acc0.w += p0*v.w;
            acc1.x += p1*v.x; acc1.y += p1*v.y; acc1.z += p1*v.z; acc1.w += p1*v.w;
            acc2.x += p2*v.x; acc2.y += p2*v.y; acc2.z += p2*v.z; acc2.w += p2*v.w;
            acc3.x += p3*v.x; acc3.y += p3*v.y; acc3.z += p3*v.z; acc3.w += p3*v.w;
        }
        __syncthreads();
    }
    *(float4*)&Out[(b*Lz + q0 + qb + 0)*Dz + lane*4] = acc0;
    *(float4*)&Out[(b*Lz + q0 + qb + 1)*Dz + lane*4] = acc1;
    *(float4*)&Out[(b*Lz + q0 + qb + 2)*Dz + lane*4] = acc2;
    *(float4*)&Out[(b*Lz + q0 + qb + 3)*Dz + lane*4] = acc3;
}

extern "C" void kernel_launch(void* const* d_in, const int* in_sizes, int n_in,
                              void* d_out, int out_size){
    const float* query = (const float*)d_in[0];
    const float* key_  = (const float*)d_in[1];
    const float* value = (const float*)d_in[2];
    const float* Wq = (const float*)d_in[3];
    const float* bq = (const float*)d_in[4];
    const float* Wk = (const float*)d_in[5];
    const float* bk = (const float*)d_in[6];
    const float* Wv = (const float*)d_in[7];
    const float* bv = (const float*)d_in[8];
    const float* wd = (const float*)d_in[9];
    const float* bd = (const float*)d_in[10];
    const float* ws = (const float*)d_in[11];
    const float* bs = (const float*)d_in[12];
    const float* wt = (const float*)d_in[13];
    const float* bt = (const float*)d_in[14];
    float* out = (float*)d_out;

    k_qk_prep<<<257, 256>>>(query, key_, Wq, bq, Wk, bk,
                            wd, bd, ws, bs, wt, bt);
    k_scores_v<<<384, 256>>>(value, Wv, bv);
    k_av<<<dim3(Lz/32, Bz), 256>>>(out);
}